// round 17
// baseline (speedup 1.0000x reference)
#include <cuda_runtime.h>
#include <cuda_bf16.h>
#include <cstdint>
#include <cstddef>

#define BSZ   4
#define CDIM  128
#define CQD   16
#define NPOS  4096
#define OUT_OFF (BSZ*CDIM*NPOS)   /* 2097152 floats; attention follows */
#define LOG2E 1.4426950408889634f

// ----------------- device scratch (no allocation allowed) -------------------
__device__ float          g_q[BSZ*NPOS*CQD];                 // [b][n][d]  (pre-scaled by log2e)
__device__ float          g_k[BSZ*NPOS*CQD];                 // [b][n][d]
__device__ __nv_bfloat16  g_v[(size_t)BSZ*CDIM*NPOS];        // [b][c][n] bf16
__device__ float          g_Spart[BSZ*4*NPOS];               // [b][g][n] partial rowsums
__device__ float          g_Vpart[(size_t)BSZ*4*CDIM*NPOS];  // [b][g][c][n] partial PV

// ----------------- helpers ---------------------------------------------------
__device__ __forceinline__ unsigned f2tf(float f) {
    unsigned r;
    asm("cvt.rna.tf32.f32 %0, %1;" : "=r"(r) : "f"(f));
    return r;
}

__device__ __forceinline__ float ex2f(float x) {
    float y;
    asm("ex2.approx.f32 %0, %1;" : "=f"(y) : "f"(x));
    return y;
}

__device__ __forceinline__ unsigned pack_bf16x2(float a, float b) {
    __nv_bfloat162 h = __float22bfloat162_rn(make_float2(a, b));
    return *(unsigned*)&h;
}

__device__ __forceinline__ void mma_tf32(float c[4],
                                         unsigned a0, unsigned a1, unsigned a2, unsigned a3,
                                         unsigned b0, unsigned b1) {
    asm volatile(
        "mma.sync.aligned.m16n8k8.row.col.f32.tf32.tf32.f32 "
        "{%0,%1,%2,%3},{%4,%5,%6,%7},{%8,%9},{%0,%1,%2,%3};"
        : "+f"(c[0]), "+f"(c[1]), "+f"(c[2]), "+f"(c[3])
        : "r"(a0), "r"(a1), "r"(a2), "r"(a3), "r"(b0), "r"(b1));
}

__device__ __forceinline__ void mma_bf16(float c[4],
                                         unsigned a0, unsigned a1, unsigned a2, unsigned a3,
                                         unsigned b0, unsigned b1) {
    asm volatile(
        "mma.sync.aligned.m16n8k16.row.col.f32.bf16.bf16.f32 "
        "{%0,%1,%2,%3},{%4,%5,%6,%7},{%8,%9},{%0,%1,%2,%3};"
        : "+f"(c[0]), "+f"(c[1]), "+f"(c[2]), "+f"(c[3])
        : "r"(a0), "r"(a1), "r"(a2), "r"(a3), "r"(b0), "r"(b1));
}

__device__ __forceinline__ void ldsm_x4(unsigned& r0, unsigned& r1,
                                        unsigned& r2, unsigned& r3, unsigned addr) {
    asm volatile("ldmatrix.sync.aligned.m8n8.x4.shared.b16 {%0,%1,%2,%3}, [%4];"
                 : "=r"(r0), "=r"(r1), "=r"(r2), "=r"(r3) : "r"(addr));
}

#define CP_ASYNC16(dst, src) \
    asm volatile("cp.async.ca.shared.global [%0], [%1], 16;" \
                 :: "r"(dst), "l"(src) : "memory")
#define CP_COMMIT()  asm volatile("cp.async.commit_group;" ::: "memory")
#define CP_WAIT1()   asm volatile("cp.async.wait_group 1;" ::: "memory")
#define CP_WAIT0()   asm volatile("cp.async.wait_group 0;" ::: "memory")

// decode work item -> (r, g), items ordered by r DESCENDING for load balance
__device__ __forceinline__ void decode_item(int item, int& r, int& g) {
    r = 63; g = item;
    while (true) {
        int ng = (r >> 4) + 1;
        if (g < ng) break;
        g -= ng; r--;
    }
}

// load q A-fragments (hi/lo tf32) from a stride-20 smem tile
__device__ __forceinline__ void load_q_frags(const float* qsm, int iw, int lr, int lk,
                                             unsigned qh[2][4], unsigned ql[2][4]) {
#pragma unroll
    for (int s = 0; s < 2; s++) {
        float f0 = qsm[(iw + lr    ) * 20 + s*8 + lk    ];
        float f1 = qsm[(iw + lr + 8) * 20 + s*8 + lk    ];
        float f2 = qsm[(iw + lr    ) * 20 + s*8 + lk + 4];
        float f3 = qsm[(iw + lr + 8) * 20 + s*8 + lk + 4];
        qh[s][0] = f2tf(f0); ql[s][0] = f2tf(f0 - __uint_as_float(qh[s][0]));
        qh[s][1] = f2tf(f1); ql[s][1] = f2tf(f1 - __uint_as_float(qh[s][1]));
        qh[s][2] = f2tf(f2); ql[s][2] = f2tf(f2 - __uint_as_float(qh[s][2]));
        qh[s][3] = f2tf(f3); ql[s][3] = f2tf(f3 - __uint_as_float(qh[s][3]));
    }
}

// hi-only variant (rowsum)
__device__ __forceinline__ void load_q_frags_hi(const float* qsm, int iw, int lr, int lk,
                                                unsigned qh[2][4]) {
#pragma unroll
    for (int s = 0; s < 2; s++) {
        qh[s][0] = f2tf(qsm[(iw + lr    ) * 20 + s*8 + lk    ]);
        qh[s][1] = f2tf(qsm[(iw + lr + 8) * 20 + s*8 + lk    ]);
        qh[s][2] = f2tf(qsm[(iw + lr    ) * 20 + s*8 + lk + 4]);
        qh[s][3] = f2tf(qsm[(iw + lr + 8) * 20 + s*8 + lk + 4]);
    }
}

// ======================= K1: q,k projection (split-tf32 MMA) =================
#define QK_SMEM ((64*132 + 32*132 + 32*132) * 4)

__global__ void __launch_bounds__(256) qk_proj_mma(
    const float* __restrict__ x,
    const float* __restrict__ wq, const float* __restrict__ bq,
    const float* __restrict__ wk, const float* __restrict__ bk)
{
    extern __shared__ float qksm[];
    float* xT  = qksm;               // [64][132]
    float* whi = xT + 64*132;        // [32][132]
    float* wlo = whi + 32*132;       // [32][132]

    int b  = blockIdx.x >> 6;
    int n0 = (blockIdx.x & 63) << 6;
    int tid  = threadIdx.x;
    int lane = tid & 31;
    int w    = tid >> 5;
    int wr   = w & 3;                // n-subtile (16 rows)
    int wd   = w >> 2;               // 0 -> q half, 1 -> k half

    const float* xb = x + (size_t)b*CDIM*NPOS;

    // stage W (fused q;k) split hi/lo; q-half scaled by log2e
#pragma unroll
    for (int it = 0; it < 16; it++) {
        int idx = it * 256 + tid;    // 0..4095
        int d = idx >> 7, c = idx & 127;
        float wv = (d < 16) ? wq[d*CDIM + c] * LOG2E : wk[(d-16)*CDIM + c];
        float hi = __uint_as_float(f2tf(wv));
        whi[d*132 + c] = hi;
        wlo[d*132 + c] = wv - hi;
    }
    // stage x^T (fp32 transpose: read float4 over n, scatter to rows)
#pragma unroll
    for (int it = 0; it < 8; it++) {
        int idx = it * 256 + tid;    // 0..2047
        int c   = idx >> 4;
        int nn4 = idx & 15;
        float4 xf = *(const float4*)(xb + (size_t)c*NPOS + n0 + nn4*4);
        xT[(nn4*4    )*132 + c] = xf.x;
        xT[(nn4*4 + 1)*132 + c] = xf.y;
        xT[(nn4*4 + 2)*132 + c] = xf.z;
        xT[(nn4*4 + 3)*132 + c] = xf.w;
    }
    __syncthreads();

    int lr = lane >> 2, lk = lane & 3;
    int nb = wr << 4;

    float acc[2][4];
    {
        const float* bias = wd ? bk : bq;
        float scale = wd ? 1.0f : LOG2E;
        float b0 = bias[2*lk] * scale,     float_b1 = 0.f;
        (void)float_b1;
        float b1 = bias[2*lk + 1] * scale;
        float b2 = bias[8 + 2*lk] * scale, b3 = bias[8 + 2*lk + 1] * scale;
        acc[0][0] = b0; acc[0][1] = b1; acc[0][2] = b0; acc[0][3] = b1;
        acc[1][0] = b2; acc[1][1] = b3; acc[1][2] = b2; acc[1][3] = b3;
    }

#pragma unroll
    for (int ks = 0; ks < 16; ks++) {
        int kc = ks * 8;
        // A frags (hi/lo)
        float f0 = xT[(nb + lr    )*132 + kc + lk    ];
        float f1 = xT[(nb + lr + 8)*132 + kc + lk    ];
        float f2 = xT[(nb + lr    )*132 + kc + lk + 4];
        float f3 = xT[(nb + lr + 8)*132 + kc + lk + 4];
        unsigned ah0 = f2tf(f0), ah1 = f2tf(f1), ah2 = f2tf(f2), ah3 = f2tf(f3);
        unsigned al0 = f2tf(f0 - __uint_as_float(ah0));
        unsigned al1 = f2tf(f1 - __uint_as_float(ah1));
        unsigned al2 = f2tf(f2 - __uint_as_float(ah2));
        unsigned al3 = f2tf(f3 - __uint_as_float(ah3));
#pragma unroll
        for (int dt = 0; dt < 2; dt++) {
            int drow = (wd << 4) + (dt << 3) + lr;   // B stored as [d][c]
            unsigned bh0 = __float_as_uint(whi[drow*132 + kc + lk    ]);
            unsigned bh1 = __float_as_uint(whi[drow*132 + kc + lk + 4]);
            unsigned bl0 = __float_as_uint(wlo[drow*132 + kc + lk    ]);
            unsigned bl1 = __float_as_uint(wlo[drow*132 + kc + lk + 4]);
            mma_tf32(acc[dt], ah0, ah1, ah2, ah3, bh0, bh1);
            mma_tf32(acc[dt], ah0, ah1, ah2, ah3, bl0, bl1);
            mma_tf32(acc[dt], al0, al1, al2, al3, bh0, bh1);
        }
    }

    // write out: rows n, cols d (within q or k half)
    float* dst = wd ? g_k : g_q;
#pragma unroll
    for (int dt = 0; dt < 2; dt++) {
        int dcol = (dt << 3) + 2*lk;
        int n_r0 = n0 + nb + lr;
        *(float2*)&dst[((size_t)(b << 12) + n_r0    ) * CQD + dcol] =
            make_float2(acc[dt][0], acc[dt][1]);
        *(float2*)&dst[((size_t)(b << 12) + n_r0 + 8) * CQD + dcol] =
            make_float2(acc[dt][2], acc[dt][3]);
    }
}

// ======================= K2: v projection (bf16 MMA + ldmatrix) ==============
#define VPROJ_SMEM (128*136*2 + 64*136*2)

__global__ void __launch_bounds__(256) v_proj(
    const float* __restrict__ x,
    const float* __restrict__ wv, const float* __restrict__ bv)
{
    extern __shared__ char vsmem_raw[];
    __nv_bfloat16* wsm  = (__nv_bfloat16*)vsmem_raw;
    __nv_bfloat16* xsmT = wsm + 128*136;

    int b  = blockIdx.x >> 6;
    int n0 = (blockIdx.x & 63) << 6;
    int tid  = threadIdx.x;
    int w    = tid >> 5;
    int lane = tid & 31;
    int gq   = lane >> 2;
    int tig  = lane & 3;
    int cb   = w << 4;

    const float* xb = x + (size_t)b*CDIM*NPOS;

    // stage wv -> wsm (bf16)
#pragma unroll
    for (int it = 0; it < 16; it++) {
        int idx = it * 256 + tid;           // 0..4095
        int c  = idx >> 5;
        int kq = idx & 31;
        float4 wf = *(const float4*)(wv + c*CDIM + kq*4);
        *(__nv_bfloat162*)(wsm + c*136 + kq*4)     = __float22bfloat162_rn(make_float2(wf.x, wf.y));
        *(__nv_bfloat162*)(wsm + c*136 + kq*4 + 2) = __float22bfloat162_rn(make_float2(wf.z, wf.w));
    }
    // stage x^T -> xsmT (bf16, transposed)
#pragma unroll
    for (int it = 0; it < 8; it++) {
        int idx = it * 256 + tid;           // 0..2047
        int k  = idx >> 4;
        int nq = idx & 15;
        float4 xf = *(const float4*)(xb + (size_t)k*NPOS + n0 + nq*4);
        xsmT[(nq*4    )*136 + k] = __float2bfloat16_rn(xf.x);
        xsmT[(nq*4 + 1)*136 + k] = __float2bfloat16_rn(xf.y);
        xsmT[(nq*4 + 2)*136 + k] = __float2bfloat16_rn(xf.z);
        xsmT[(nq*4 + 3)*136 + k] = __float2bfloat16_rn(xf.w);
    }
    __syncthreads();

    float acc[8][4];
    {
        float blo = bv[cb + gq], bhi = bv[cb + gq + 8];
#pragma unroll
        for (int nt = 0; nt < 8; nt++) {
            acc[nt][0] = blo; acc[nt][1] = blo;
            acc[nt][2] = bhi; acc[nt][3] = bhi;
        }
    }

    unsigned wsm_sh  = (unsigned)__cvta_generic_to_shared(wsm);
    unsigned xsm_sh  = (unsigned)__cvta_generic_to_shared(xsmT);
    unsigned a_base  = wsm_sh + ((cb + (lane & 15)) * 136 + ((lane >> 4) << 3)) * 2;
    unsigned b_row   = (lane & 7) + ((lane >> 4) << 3);
    unsigned b_base  = xsm_sh + (b_row * 136 + (((lane >> 3) & 1) << 3)) * 2;

#pragma unroll
    for (int ks8 = 0; ks8 < 8; ks8++) {
        unsigned a0, a1, a2, a3;
        ldsm_x4(a0, a1, a2, a3, a_base + (ks8 * 16) * 2);
#pragma unroll
        for (int np = 0; np < 4; np++) {
            unsigned b0, b1, b2, b3;
            ldsm_x4(b0, b1, b2, b3, b_base + ((np * 16) * 136 + ks8 * 16) * 2);
            mma_bf16(acc[np*2    ], a0, a1, a2, a3, b0, b1);
            mma_bf16(acc[np*2 + 1], a0, a1, a2, a3, b2, b3);
        }
    }

    __nv_bfloat16* vb = g_v + (size_t)b*CDIM*NPOS;
#pragma unroll
    for (int nt = 0; nt < 8; nt++) {
        int n = n0 + nt*8 + tig*2;
        *(__nv_bfloat162*)&vb[(size_t)(cb+gq  )*NPOS + n] =
            __float22bfloat162_rn(make_float2(acc[nt][0], acc[nt][1]));
        *(__nv_bfloat162*)&vb[(size_t)(cb+gq+8)*NPOS + n] =
            __float22bfloat162_rn(make_float2(acc[nt][2], acc[nt][3]));
    }
}

// ======================= K3: rowsum (2 MMAs, ILP-2 pairs, cp.async) ==========
#define KT_F   (64*20)
#define KT_B   (KT_F*4)

__global__ void __launch_bounds__(256, 3) rowsum_k()
{
    __shared__ float qsm[64*20];
    __shared__ float ks3[3*KT_F];
    __shared__ float red[64][2];

    int b = blockIdx.x & 3;
    int item = blockIdx.x >> 2;
    int r, g; decode_item(item, r, g);

    int tid = threadIdx.x;
    int i0 = r << 6;
    int col0 = g << 10;
    int colEnd = min((r + 1) << 6, col0 + 1024);
    int nt = (colEnd - col0) >> 6;

    unsigned ks_sh = (unsigned)__cvta_generic_to_shared(ks3);
    unsigned kdst  = (tid >> 2) * 80 + (tid & 3) * 16;
    const float* ksrc = g_k + ((size_t)(b << 12) + (tid >> 2)) * CQD + (tid & 3) * 4;

    // stage q tile
    {
        const float4 qv = ((const float4*)(g_q +
            ((size_t)(b << 12) + i0 + (tid >> 2)) * CQD))[tid & 3];
        *(float4*)&qsm[(tid >> 2) * 20 + (tid & 3) * 4] = qv;
    }
    // prologue: tiles 0 (+1)
    CP_ASYNC16(ks_sh + kdst, ksrc + (size_t)col0 * CQD);
    CP_COMMIT();
    if (nt > 1) {
        CP_ASYNC16(ks_sh + KT_B + kdst, ksrc + (size_t)(col0 + 64) * CQD);
        CP_COMMIT();
    }
    __syncthreads();

    int w = tid >> 5, lane = tid & 31;
    int wr = w & 3, wc = w >> 2;
    int iw = wr << 4;
    int lr = lane >> 2, lk = lane & 3;

    unsigned qh[2][4];
    load_q_frags_hi(qsm, iw, lr, lk, qh);

    float rs0 = 0.f, rs1 = 0.f;
    int slot = 0;

    for (int t = 0; t < nt; t++) {
        if (t + 1 < nt) CP_WAIT1(); else CP_WAIT0();
        __syncthreads();                        // tile t visible; compute(t-1) done
        if (t + 2 < nt) {
            int s2 = slot + 2; if (s2 >= 3) s2 -= 3;
            CP_ASYNC16(ks_sh + s2*KT_B + kdst, ksrc + (size_t)(col0 + (t+2)*64) * CQD);
            CP_COMMIT();
        }
        const float* ksb = ks3 + slot*KT_F;

#pragma unroll
        for (int pair = 0; pair < 2; pair++) {
            int j0 = (wc << 5) + (pair << 4);
            float e0[4] = {0.f, 0.f, 0.f, 0.f};
            float e1[4] = {0.f, 0.f, 0.f, 0.f};
#pragma unroll
            for (int s = 0; s < 2; s++) {
                float fa0 = ksb[(j0 + lr    ) * 20 + s*8 + lk    ];
                float fa1 = ksb[(j0 + lr    ) * 20 + s*8 + lk + 4];
                float fb0 = ksb[(j0 + 8 + lr) * 20 + s*8 + lk    ];
                float fb1 = ksb[(j0 + 8 + lr) * 20 + s*8 + lk + 4];
                unsigned ah0 = f2tf(fa0), ah1 = f2tf(fa1);
                unsigned al0 = f2tf(fa0 - __uint_as_float(ah0));
                unsigned al1 = f2tf(fa1 - __uint_as_float(ah1));
                unsigned bh0 = f2tf(fb0), bh1 = f2tf(fb1);
                unsigned bl0 = f2tf(fb0 - __uint_as_float(bh0));
                unsigned bl1 = f2tf(fb1 - __uint_as_float(bh1));
                mma_tf32(e0, qh[s][0], qh[s][1], qh[s][2], qh[s][3], ah0, ah1);
                mma_tf32(e1, qh[s][0], qh[s][1], qh[s][2], qh[s][3], bh0, bh1);
                mma_tf32(e0, qh[s][0], qh[s][1], qh[s][2], qh[s][3], al0, al1);
                mma_tf32(e1, qh[s][0], qh[s][1], qh[s][2], qh[s][3], bl0, bl1);
            }
            rs0 += ex2f(e0[0]) + ex2f(e0[1]) + ex2f(e1[0]) + ex2f(e1[1]);
            rs1 += ex2f(e0[2]) + ex2f(e0[3]) + ex2f(e1[2]) + ex2f(e1[3]);
        }
        if (++slot == 3) slot = 0;
    }

    rs0 += __shfl_xor_sync(0xffffffffu, rs0, 1);
    rs0 += __shfl_xor_sync(0xffffffffu, rs0, 2);
    rs1 += __shfl_xor_sync(0xffffffffu, rs1, 1);
    rs1 += __shfl_xor_sync(0xffffffffu, rs1, 2);
    if (lk == 0) {
        red[iw + lr    ][wc] = rs0;
        red[iw + lr + 8][wc] = rs1;
    }
    __syncthreads();
    if (tid < 64)
        g_Spart[(((size_t)b*4 + g) << 12) + i0 + tid] = red[tid][0] + red[tid][1];
}

// ======================= K5: main pass =======================================
// FA2-style: p stays in registers as the PV A operand. e-phase runs ILP-2
// accumulator pairs; exp is raw ex2 (q pre-scaled by log2e). No zerofill here.
#define VT_B (128*72*2)
#define ATTN_SMEM (5120 + 3*KT_B + 3*VT_B + 256)

__global__ void __launch_bounds__(256, 2) attn_main(float* __restrict__ out)
{
    extern __shared__ char smem_raw[];
    float*          qsm  = (float*)smem_raw;
    float*          ks3  = qsm + 64*20;
    __nv_bfloat16*  vsm  = (__nv_bfloat16*)(ks3 + 3*KT_F);
    float*          sinv = (float*)(vsm + 3*128*72);

    int b = blockIdx.x & 3;
    int item = blockIdx.x >> 2;
    int r, g; decode_item(item, r, g);

    int tid = threadIdx.x;
    int i0 = r << 6;
    int col0 = g << 10;
    int colEnd = min((r + 1) << 6, col0 + 1024);
    int nt = (colEnd - col0) >> 6;
    int ngg = (r >> 4) + 1;

    float* attnb = out + OUT_OFF + ((size_t)b << 24);
    const __nv_bfloat16* vbat = g_v + (size_t)b*CDIM*NPOS;

    unsigned ks_sh = (unsigned)__cvta_generic_to_shared(ks3);
    unsigned vs_sh = (unsigned)__cvta_generic_to_shared(vsm);
    unsigned kdst  = (tid >> 2) * 80 + (tid & 3) * 16;
    const float* ksrc = g_k + ((size_t)(b << 12) + (tid >> 2)) * CQD + (tid & 3) * 4;

    auto stage_tile = [&](int jc, int slot) {
        CP_ASYNC16(ks_sh + slot*KT_B + kdst, ksrc + (size_t)jc * CQD);
#pragma unroll
        for (int it = 0; it < 4; it++) {
            int idx = it * 256 + tid;
            int c = idx >> 3, ch = idx & 7;
            CP_ASYNC16(vs_sh + slot*VT_B + c*144 + ch*16,
                       vbat + (size_t)c*NPOS + jc + ch*8);
        }
        CP_COMMIT();
    };

    if (tid < 64) {
        float s = 0.f;
        for (int gg = 0; gg < ngg; gg++)
            s += g_Spart[(((size_t)b*4 + gg) << 12) + i0 + tid];
        sinv[tid] = 1.0f / s;
    }
    // stage q tile
    {
        const float4 qv = ((const float4*)(g_q +
            ((size_t)(b << 12) + i0 + (tid >> 2)) * CQD))[tid & 3];
        *(float4*)&qsm[(tid >> 2) * 20 + (tid & 3) * 4] = qv;
    }
    // prologue: tiles 0 (+1)
    stage_tile(col0, 0);
    if (nt > 1) stage_tile(col0 + 64, 1);
    __syncthreads();

    int w = tid >> 5, lane = tid & 31;
    int wr = w & 3, wc = w >> 2;
    int iw = wr << 4;                 // warp i-base (both phases)
    int lr = lane >> 2, lk = lane & 3;

    float inv0 = sinv[iw + lr], inv1 = sinv[iw + lr + 8];

    unsigned qh[2][4], ql[2][4];
    load_q_frags(qsm, iw, lr, lk, qh, ql);

    // PV B-frag (V^T) ldmatrix base: rows = c, cols = j within slot
    unsigned bV0 = vs_sh + ((lane & 7) + ((lane >> 4) << 3)) * 144
                 + ((wc << 5) + (((lane >> 3) & 1) << 3)) * 2;

    float acc[16][4];
#pragma unroll
    for (int a = 0; a < 16; a++)
#pragma unroll
        for (int c = 0; c < 4; c++) acc[a][c] = 0.f;

    int slot = 0;
    for (int t = 0; t < nt; t++) {
        int jcol0 = col0 + t * 64;
        if (t + 1 < nt) CP_WAIT1(); else CP_WAIT0();
        __syncthreads();   // tile t visible; all warps past PV(t-1)
        if (t + 2 < nt) {
            int s2 = slot + 2; if (s2 >= 3) s2 -= 3;
            stage_tile(jcol0 + 128, s2);
        }

        const float* ksb = ks3 + slot*KT_F;
        unsigned pa[2][4];   // PV A-frags: [k-block][a0..a3]

        // ---- e via 3 tf32 MMAs, ILP-2 pairs; write attn, keep p in regs ----
        float* arow0 = attnb + (size_t)(i0 + iw + lr) * NPOS + jcol0;
        float* arow1 = arow0 + (size_t)8 * NPOS;
#pragma unroll
        for (int pair = 0; pair < 2; pair++) {
            int j0 = (wc << 5) + (pair << 4);
            float e0[4] = {0.f, 0.f, 0.f, 0.f};
            float e1[4] = {0.f, 0.f, 0.f, 0.f};
#pragma unroll
            for (int s = 0; s < 2; s++) {
                float fa0 = ksb[(j0 + lr    ) * 20 + s*8 + lk    ];
                float fa1 = ksb[(j0 + lr    ) * 20 + s*8 + lk + 4];
                float fb0 = ksb[(j0 + 8 + lr) * 20 + s*8 + lk    ];
                float fb1 = ksb[(j0 + 8 + lr) * 20 + s*8 + lk + 4];
                unsigned ah0 = f2tf(fa0), ah1 = f2tf(fa1);
                unsigned al0 = f2tf(fa0 - __uint_as_float(ah0));
                unsigned al1 = f2tf(fa1 - __uint_as_float(ah1));
                unsigned bh0 = f2tf(fb0), bh1 = f2tf(fb1);
                unsigned bl0 = f2tf(fb0 - __uint_as_float(bh0));
                unsigned bl1 = f2tf(fb1 - __uint_as_float(bh1));
                mma_tf32(e0, qh[s][0], qh[s][1], qh[s][2], qh[s][3], ah0, ah1);
                mma_tf32(e1, qh[s][0], qh[s][1], qh[s][2], qh[s][3], bh0, bh1);
                mma_tf32(e0, qh[s][0], qh[s][1], qh[s][2], qh[s][3], al0, al1);
                mma_tf32(e1, qh[s][0], qh[s][1], qh[s][2], qh[s][3], bl0, bl1);
                mma_tf32(e0, ql[s][0], ql[s][1], ql[s][2], ql[s][3], ah0, ah1);
                mma_tf32(e1, ql[s][0], ql[s][1], ql[s][2], ql[s][3], bh0, bh1);
            }
            float p00 = ex2f(e0[0]) * inv0;
            float p01 = ex2f(e0[1]) * inv0;
            float p02 = ex2f(e0[2]) * inv1;
            float p03 = ex2f(e0[3]) * inv1;
            float p10 = ex2f(e1[0]) * inv0;
            float p11 = ex2f(e1[1]) * inv0;
            float p12 = ex2f(e1[2]) * inv1;
            float p13 = ex2f(e1[3]) * inv1;
            int jloc0 = j0 + (lk << 1);
            *(float2*)(arow0 + jloc0)     = make_float2(p00, p01);
            *(float2*)(arow1 + jloc0)     = make_float2(p02, p03);
            *(float2*)(arow0 + jloc0 + 8) = make_float2(p10, p11);
            *(float2*)(arow1 + jloc0 + 8) = make_float2(p12, p13);
            // bf16 A-frag layout: a0=(row lr,k0-7) a1=(row lr+8,k0-7)
            //                     a2=(row lr,k8-15) a3=(row lr+8,k8-15)
            pa[pair][0] = pack_bf16x2(p00, p01);   // row lr,   k 0-7
            pa[pair][1] = pack_bf16x2(p02, p03);   // row lr+8, k 0-7
            pa[pair][2] = pack_bf16x2(p10, p11);   // row lr,   k 8-15
            pa[pair][3] = pack_bf16x2(p12, p13);   // row lr+8, k 8-15
        }

        // ---- PV: out[i][c] += p[i][j] * V^T[j][c]; A from regs, B via ldsm --
        unsigned bbase = bV0 + slot*VT_B;
#pragma unroll
        for (int kb = 0; kb < 2; kb++) {
#pragma unroll
            for (int cg = 0; cg < 8; cg++) {
                unsigned b0, b1, b2, b3;
                ldsm_x4(b0, b1, b2, b3, bbase + cg*2304 + kb*32);
                mma_bf16(acc[cg*2    ], pa[kb][0], pa[kb][1], pa[kb][2], pa[kb][3], b0, b1);
                mma_bf16(acc[cg*2 + 1], pa[kb][0], pa[kb][1], pa[kb][2], pa[kb][3], b2, b3);
            }
        }
        if (++slot == 3) slot = 0;
    }

    // ---- cross-warp reduce (wc=1 -> wc=0) and store partial PV -------------
    __syncthreads();                    // all PV reads of vsm done
    float* redbuf = (float*)vsm;        // 32KB scratch inside freed vsm
    if (wc == 1) {
        float* dst = redbuf + wr*2048 + lane;
#pragma unroll
        for (int a = 0; a < 16; a++)
#pragma unroll
            for (int c = 0; c < 4; c++)
                dst[(a*4 + c) * 32] = acc[a][c];
    }
    __syncthreads();
    if (wc == 0) {
        const float* src = redbuf + wr*2048 + lane;
        float* vp = g_Vpart + (((size_t)b*4 + g) * CDIM) * NPOS;
        int gi = lane >> 2, t2 = (lane & 3) << 1;
        int ii = i0 + iw + gi;
#pragma unroll
        for (int a = 0; a < 16; a++) {
            float v0 = acc[a][0] + src[(a*4 + 0) * 32];
            float v1 = acc[a][1] + src[(a*4 + 1) * 32];
            float v2 = acc[a][2] + src[(a*4 + 2) * 32];
            float v3 = acc[a][3] + src[(a*4 + 3) * 32];
            int cc = a*8 + t2;
            vp[(size_t)cc*NPOS + ii]         = v0;
            vp[(size_t)(cc+1)*NPOS + ii]     = v1;
            vp[(size_t)cc*NPOS + ii + 8]     = v2;
            vp[(size_t)(cc+1)*NPOS + ii + 8] = v3;
        }
    }
}

// ======================= K6: zero-fill masked attention (overlapped) =========
__global__ void __launch_bounds__(256) zerofill(float* __restrict__ out)
{
    int row = blockIdx.x;                 // 0 .. B*N-1
    int n   = row & (NPOS - 1);
    int L   = ((n >> 6) + 1) << 6;
    if (L >= NPOS) return;
    float4* dst = (float4*)(out + OUT_OFF + ((size_t)row << 12) + L);
    int cnt4 = (NPOS - L) >> 2;
    float4 z = make_float4(0.f, 0.f, 0.f, 0.f);
    for (int t = threadIdx.x; t < cnt4; t += 256) dst[t] = z;
}

// ======================= K7: finalize ========================================
__global__ void __launch_bounds__(256) finalize(
    const float* __restrict__ x, const float* __restrict__ gamma,
    float* __restrict__ out)
{
    int t = blockIdx.x * 256 + threadIdx.x;    // < B*C*N
    int n  = t & (NPOS - 1);
    int bc = t >> 12;
    int b  = bc >> 7;
    int c  = bc & 127;
    int ngg = (n >> 10) + 1;

    const float* vp = g_Vpart + ((size_t)(b*4) * CDIM + c) * NPOS + n;
    float s = 0.f;
    for (int gg = 0; gg < ngg; gg++)
        s += vp[(size_t)gg * CDIM * NPOS];
    out[t] = gamma[0] * s + x[t];
}

// ======================= launch ==============================================
extern "C" void kernel_launch(void* const* d_in, const int* in_sizes, int n_in,
                              void* d_out, int out_size)
{
    const float* x     = (const float*)d_in[0];
    const float* wq    = (const float*)d_in[1];
    const float* bq    = (const float*)d_in[2];
    const float* wk    = (const float*)d_in[3];
    const float* bk    = (const float*)d_in[4];
    const float* wv    = (const float*)d_in[5];
    const float* bv    = (const float*)d_in[6];
    const float* gamma = (const float*)d_in[7];
    float* out = (float*)d_out;

    cudaFuncSetAttribute(attn_main,
                         cudaFuncAttributeMaxDynamicSharedMemorySize, ATTN_SMEM);
    cudaFuncSetAttribute(v_proj,
                         cudaFuncAttributeMaxDynamicSharedMemorySize, VPROJ_SMEM);
    cudaFuncSetAttribute(qk_proj_mma,
                         cudaFuncAttributeMaxDynamicSharedMemorySize, QK_SMEM);

    // Fork a side stream inside graph capture (documented event pattern):
    //   s2: zerofill (DRAM-bound) + v_proj (independent of q/k)
    //   main: qk_proj -> rowsum (compute-bound)
    // Join before attn_main so it owns full DRAM bandwidth.
    // Streams/events are created per call and intentionally NOT destroyed
    // (destroying a stream that participated in capture is the risky op;
    //  kernel_launch runs only ~2-3 times, so the leak is bounded & harmless).
    cudaStream_t s2;
    cudaStreamCreateWithFlags(&s2, cudaStreamNonBlocking);
    cudaEvent_t eFork, eJoin;
    cudaEventCreateWithFlags(&eFork, cudaEventDisableTiming);
    cudaEventCreateWithFlags(&eJoin, cudaEventDisableTiming);

    cudaEventRecord(eFork, 0);
    cudaStreamWaitEvent(s2, eFork, 0);

    // side stream: mask zeros + V projection
    zerofill<<<BSZ*NPOS, 256, 0, s2>>>(out);
    v_proj<<<BSZ*(NPOS/64), 256, VPROJ_SMEM, s2>>>(x, wv, bv);
    cudaEventRecord(eJoin, s2);

    // main stream: q/k projection + row sums
    qk_proj_mma<<<BSZ*64, 256, QK_SMEM>>>(x, wq, bq, wk, bk);
    rowsum_k<<<BSZ*160, 256>>>();

    // join, then the heavy pass
    cudaStreamWaitEvent(0, eJoin, 0);
    attn_main<<<BSZ*160, 256, ATTN_SMEM>>>(out);
    finalize<<<(BSZ*CDIM*NPOS)/256, 256>>>(x, gamma, out);
}